// round 17
// baseline (speedup 1.0000x reference)
#include <cuda_runtime.h>

// Math collapse (verified R8-R16): softmax over a size-1 axis == 1.0 exactly,
//   out[b,c,f] = sum_t x[b,t,f]     (context/W/b are dead inputs).
//
// Established wall: output writes cap at ~1.9TB/s GLOBALLY (path/pattern/
// occupancy/SM-count invariant; R10-R16). 16MB => >=8.6us of wall time.
// Reads stream at ~8TB/s and use a DIFFERENT resource (DRAM read vs L2 write
// fabric). Strategy: keep the write wall packed from t~=0.5us by pipelining:
// b-sorted reads (tiny 512B partials, so partial traffic barely taxes the
// wall), with each CTA firing its one 128KB store as soon as its b-group's
// partials arrive. Tight volatile spins (no __nanosleep - R14's mistake),
// grid 128 <= 148 SMs so all CTAs are co-resident (no spin deadlock).

#define B_ 32
#define T_ 512
#define C_ 256
#define F_ 512

static constexpr int F4      = F_ / 4;     // 128 float4 per row
static constexpr int NQ      = 4;          // 512B strips per row
static constexpr int SW4     = F4 / NQ;    // 32 float4 per strip
static constexpr int NH      = 8;          // T chunks
static constexpr int ROWS_H  = T_ / NH;    // 64 rows per read unit
static constexpr int GRID    = 128;
static constexpr int TPB     = 256;
static constexpr int ITERS   = 8;          // 1024 read units / 128 CTAs

// Partials: [b*NQ+q][h][f4]  (128*8*32 float4 = 512KB)
__device__ float4 g_part[GRID][NH][SW4];
__device__ int    g_cnt[GRID];             // per (b,q) publish count -> 8

__device__ __forceinline__ void f4add(float4& a, const float4& b) {
    a.x += b.x; a.y += b.y; a.z += b.z; a.w += b.w;
}

__global__ __launch_bounds__(TPB)
void pipelined_fused(const float* __restrict__ x, float* __restrict__ out) {
    const int u  = blockIdx.x;             // 0..127
    const int t  = threadIdx.x;
    const int f4 = t & (SW4 - 1);          // 0..31 (column within strip)
    const int rg = t >> 5;                 // warp id 0..7 = row group

    __shared__ float4 sm[TPB];             // 4KB reduce buffer
    __shared__ float4 fin[SW4];            // final strip row (512B)

    for (int i = 0; i < ITERS; ++i) {
        // ---- read unit g: b-sorted so early b's complete first -----------
        const int g = i * GRID + u;        // 0..1023
        const int b = g >> 5;              // 32 units per b
        const int q = (g >> 3) & 3;
        const int h = g & 7;

        // rows h*64 + rg + 8j, strip columns q*32+f4. Warp-op = 512B
        // contiguous (proven 8TB/s pattern); 8 independent loads (MLP=8).
        const float4* base = reinterpret_cast<const float4*>(x)
            + ((size_t)b * T_ + h * ROWS_H + rg) * F4 + q * SW4 + f4;
        float4 a0 = __ldg(&base[(size_t)( 0) * F4]);
        float4 a1 = __ldg(&base[(size_t)( 8) * F4]);
        float4 a2 = __ldg(&base[(size_t)(16) * F4]);
        float4 a3 = __ldg(&base[(size_t)(24) * F4]);
        float4 a4 = __ldg(&base[(size_t)(32) * F4]);
        float4 a5 = __ldg(&base[(size_t)(40) * F4]);
        float4 a6 = __ldg(&base[(size_t)(48) * F4]);
        float4 a7 = __ldg(&base[(size_t)(56) * F4]);
        f4add(a0, a4); f4add(a1, a5); f4add(a2, a6); f4add(a3, a7);
        f4add(a0, a2); f4add(a1, a3);
        f4add(a0, a1);

        sm[t] = a0;
        __syncthreads();
        if (t < SW4) {                     // combine the 8 row-groups
            float4 s = sm[t];
#pragma unroll
            for (int gg = 1; gg < 8; ++gg) f4add(s, sm[gg * SW4 + t]);
            g_part[b * NQ + q][h][t] = s;  // 512B partial
        }
        __threadfence();                   // make partial globally visible
        __syncthreads();
        if (t == 0) atomicAdd(&g_cnt[b * NQ + q], 1);

        // ---- my store turn? (CTA u owns store unit b=u/4, q=u%3) ---------
        if (i == (u >> 4)) {               // b_s = u>>2 in group i = u>>4
            if (t == 0) {                  // tight spin, no nanosleep
                while (*(volatile int*)&g_cnt[u] < NH) { }
            }
            __syncthreads();
            __threadfence();               // acquire published partials

            // combine 8 partials (4KB, L2-hot): one float4 per thread
            sm[t] = g_part[u][t >> 5][f4];
            __syncthreads();
            if (t < SW4) {
                float4 s = sm[t];
#pragma unroll
                for (int gg = 1; gg < 8; ++gg) f4add(s, sm[gg * SW4 + t]);
                fin[t] = s;                // final strip row
            }
            __syncthreads();

            // store 256 c-rows x 512B strip = 128KB; warp-op = 512B
            // contiguous, rows strided 2KB (pattern proven irrelevant).
            const float4 myval = fin[f4];
            const int b_s = u >> 2, q_s = u & 3;
            float4* ob = reinterpret_cast<float4*>(out)
                + ((size_t)b_s * C_ + rg) * F4 + q_s * SW4 + f4;
#pragma unroll
            for (int k = 0; k < C_ / 8; ++k)        // 32 independent stores
                ob[(size_t)(8 * k) * F4] = myval;

            __syncthreads();
            if (t == 0) g_cnt[u] = 0;      // reset for next graph replay
        }
    }
}

extern "C" void kernel_launch(void* const* d_in, const int* in_sizes, int n_in,
                              void* d_out, int out_size) {
    (void)in_sizes; (void)n_in; (void)out_size;
    const float* x = (const float*)d_in[0];   // [B,T,F]; context/W/b dead
    float* out = (float*)d_out;               // [B,C,F]
    // 128 CTAs x 256 threads, <=1 CTA/SM: all co-resident, spins are safe.
    pipelined_fused<<<GRID, TPB>>>(x, out);
}